// round 4
// baseline (speedup 1.0000x reference)
#include <cuda_runtime.h>
#include <cuda_bf16.h>
#include <cstdint>

// ======================= problem constants =======================
static constexpr int MUL  = 192;
static constexpr int FEAT = 1728;

static constexpr int NCTA = 148;
static constexpr int C0 = 16, C1 = 49;       // C2 = 148-16-49 = 83

// SMEM layout (dynamic):
//  [0, 73728)           Wh  : 192 rows(n=o) x 384B (k=m bf16), XOR-swizzled 16B chunks
//  [73728, 147456)      Wl  : same
//  [147456, +32768)     A buf0: hi 16KB (128 rows x 128B) + lo 16KB
//  [180224, +32768)     A buf1
static constexpr int SM_W    = 0;
static constexpr int W_ONE   = 73728;
static constexpr int SM_A    = 2 * W_ONE;          // 147456
static constexpr int A_BUF   = 32768;
static constexpr int SMEM_TOTAL = SM_A + 2 * A_BUF; // 212992

// Folded + hi/lo split weights, layout [k][o][m] bf16 (B operand is [n][k] row-major)
__device__ __align__(16) __nv_bfloat16 g_Wh[3 * MUL * MUL];
__device__ __align__(16) __nv_bfloat16 g_Wl[3 * MUL * MUL];

// ======================= prep: fold LoRA, split hi/lo =======================
__global__ void prep_weights_kernel(const float* __restrict__ Wb,
                                    const float* __restrict__ WA,
                                    const float* __restrict__ WB) {
    int idx = blockIdx.x * blockDim.x + threadIdx.x;
    if (idx >= 3 * MUL * MUL) return;
    int k   = idx / (MUL * MUL);
    int rem = idx - k * (MUL * MUL);
    int o   = rem / MUL;            // output channel (n)
    int m   = rem - o * MUL;        // input channel  (k of GEMM)

    const float pw_base = rsqrtf(192.0f);
    const float pw_B    = rsqrtf(8.0f);

    float acc = 0.0f;
#pragma unroll
    for (int r = 0; r < 8; r++)
        acc += WA[(k * MUL + m) * 8 + r] * WB[(k * 8 + r) * MUL + o];
    float w = pw_base * Wb[(k * MUL + m) * MUL + o] + 2.0f * pw_base * pw_B * acc;

    __nv_bfloat16 hi = __float2bfloat16(w);
    float lo_f = w - __bfloat162float(hi);
    __nv_bfloat16 lo = __float2bfloat16(lo_f);

    g_Wh[idx] = hi;   // [k][o][m]
    g_Wl[idx] = lo;
}

// ======================= device helpers =======================
__device__ __forceinline__ uint32_t smem_to_u32(const void* p) {
    uint32_t a;
    asm("{ .reg .u64 t; cvta.to.shared.u64 t, %1; cvt.u32.u64 %0, t; }"
        : "=r"(a) : "l"(p));
    return a;
}

__device__ __forceinline__ unsigned row_to_node(unsigned g, int d) {
    if (d == 1) return g;
    if (d == 3) return __umulhi(g, 0xAAAAAAABu) >> 1;
    return __umulhi(g, 0xCCCCCCCDu) >> 2;   // d == 5
}

// pack {bf16(a), bf16(b)} (a in low half) and exact fp32 residuals packed too
__device__ __forceinline__ void split2(float a, float b, uint32_t& hp, uint32_t& lp) {
    asm("cvt.rn.bf16x2.f32 %0, %1, %2;" : "=r"(hp) : "f"(b), "f"(a));
    float ha = __uint_as_float(hp << 16);
    float hb = __uint_as_float(hp & 0xFFFF0000u);
    float la = a - ha;
    float lb = b - hb;
    asm("cvt.rn.bf16x2.f32 %0, %1, %2;" : "=r"(lp) : "f"(lb), "f"(la));
}

__device__ __forceinline__ void ldsm4(uint32_t& r0, uint32_t& r1,
                                      uint32_t& r2, uint32_t& r3, uint32_t addr) {
    asm volatile("ldmatrix.sync.aligned.m8n8.x4.shared.b16 {%0,%1,%2,%3}, [%4];"
                 : "=r"(r0), "=r"(r1), "=r"(r2), "=r"(r3) : "r"(addr));
}

__device__ __forceinline__ void mma16816(float c[4], const uint32_t a[4],
                                         const uint32_t b[2]) {
    asm volatile("mma.sync.aligned.m16n8k16.row.col.f32.bf16.bf16.f32 "
                 "{%0,%1,%2,%3}, {%4,%5,%6,%7}, {%8,%9}, {%0,%1,%2,%3};"
                 : "+f"(c[0]), "+f"(c[1]), "+f"(c[2]), "+f"(c[3])
                 : "r"(a[0]), "r"(a[1]), "r"(a[2]), "r"(a[3]),
                   "r"(b[0]), "r"(b[1]));
}

// ======================= main kernel =======================
extern "C" __global__ void __launch_bounds__(256, 1)
lora_linear_main(const float* __restrict__ x, float* __restrict__ out, int n) {
    extern __shared__ char smem[];
    const uint32_t sb  = smem_to_u32(smem);
    const int tid  = threadIdx.x;
    const int lane = tid & 31;
    const int wid  = tid >> 5;
    const int wm   = wid & 3;       // warp M position (32 rows each)
    const int wn   = wid >> 2;      // warp N position (96 cols each)

    // ---- CTA -> (irrep, tile range) ----
    int b = blockIdx.x;
    int k, idx, nC;
    if (b < C0)            { k = 0; idx = b;            nC = C0; }
    else if (b < C0 + C1)  { k = 1; idx = b - C0;       nC = C1; }
    else                   { k = 2; idx = b - C0 - C1;  nC = NCTA - C0 - C1; }
    const int d      = (k == 0) ? 1 : (k == 1) ? 3 : 5;
    const int segoff = (k == 0) ? 0 : (k == 1) ? 192 : 768;
    const int rows   = n * d;
    const int T      = (rows + 127) >> 7;
    const int t0 = (int)(((long long)idx * T) / nC);
    const int t1 = (int)(((long long)(idx + 1) * T) / nC);

    // ---- copy W into smem with XOR row-swizzle (16B chunk ^= (n & 7)) ----
    {
        const float4* gh = reinterpret_cast<const float4*>(g_Wh + (size_t)k * MUL * MUL);
        const float4* gl = reinterpret_cast<const float4*>(g_Wl + (size_t)k * MUL * MUL);
        for (int i = tid; i < W_ONE / 16; i += 256) {   // 4608 chunks
            int nrow = i / 24;
            int c    = i - nrow * 24;
            int c2   = c ^ (nrow & 7);
            int dst  = nrow * 384 + c2 * 16;
            *reinterpret_cast<float4*>(smem + SM_W + dst)         = gh[i];
            *reinterpret_cast<float4*>(smem + SM_W + W_ONE + dst) = gl[i];
        }
    }
    __syncthreads();

    if (t0 >= t1) return;

    float acc[2][12][4];
    float4 pf[8];

    // prefetch loader: chunk c of tile t -> pf[8]
    auto load_chunk = [&](int t, int c) {
#pragma unroll
        for (int q = 0; q < 8; q++) {
            int f    = tid + q * 256;        // float4 index 0..2047
            int r    = f >> 4;               // row in tile
            int col4 = f & 15;               // float4 within 64-col chunk
            int grow = t * 128 + r;
            float4 v = make_float4(0.f, 0.f, 0.f, 0.f);
            if (grow < rows) {
                unsigned gr   = (unsigned)grow;
                unsigned node = row_to_node(gr, d);
                unsigned sub  = gr - node * (unsigned)d;
                v = *reinterpret_cast<const float4*>(
                        x + (size_t)node * FEAT + segoff + sub * 192 + c * 64 + col4 * 4);
            }
            pf[q] = v;
        }
    };

    load_chunk(t0, 0);
    int cc = 0;

    for (int t = t0; t < t1; ++t) {
#pragma unroll
        for (int mi = 0; mi < 2; mi++)
#pragma unroll
            for (int nb = 0; nb < 12; nb++)
#pragma unroll
                for (int j = 0; j < 4; j++) acc[mi][nb][j] = 0.0f;

        for (int c = 0; c < 3; ++c, ++cc) {
            const int buf = cc & 1;
            const uint32_t hiB = sb + (uint32_t)(SM_A + buf * A_BUF);
            const uint32_t loB = hiB + 16384u;

            // ---- convert pf -> smem (hi & lo, swizzled) ----
#pragma unroll
            for (int q = 0; q < 8; q++) {
                int f    = tid + q * 256;
                int r    = f >> 4;
                int col4 = f & 15;
                uint32_t h0, h1, l0, l1;
                split2(pf[q].x, pf[q].y, h0, l0);
                split2(pf[q].z, pf[q].w, h1, l1);
                uint32_t off = (uint32_t)(r * 128 + (((col4 >> 1) ^ (r & 7)) << 4) +
                                          ((col4 & 1) << 3));
                asm volatile("st.shared.v2.b32 [%0], {%1,%2};"
                             :: "r"(hiB + off), "r"(h0), "r"(h1) : "memory");
                asm volatile("st.shared.v2.b32 [%0], {%1,%2};"
                             :: "r"(loB + off), "r"(l0), "r"(l1) : "memory");
            }
            __syncthreads();

            // ---- prefetch next chunk during MMA ----
            if (c < 2)            load_chunk(t, c + 1);
            else if (t + 1 < t1)  load_chunk(t + 1, 0);

            // ---- MMA: 3 passes (Ah*Wh, Al*Wh, Ah*Wl) ----
#pragma unroll
            for (int pass = 0; pass < 3; pass++) {
                const uint32_t Ab = (pass == 1) ? loB : hiB;
                const uint32_t Wm = sb + (uint32_t)(SM_W + ((pass == 2) ? W_ONE : 0));
#pragma unroll
                for (int ki = 0; ki < 4; ki++) {
                    const int kg  = c * 64 + ki * 16;     // global k for B
                    const int cib = kg >> 3;              // 16B chunk base in W row
                    uint32_t bfr[12][2];
#pragma unroll
                    for (int nb2 = 0; nb2 < 6; nb2++) {
                        int nrow = 96 * wn + nb2 * 16 + 8 * (lane >> 4) + (lane & 7);
                        int ci   = cib + ((lane >> 3) & 1);
                        uint32_t addr = Wm + (uint32_t)(nrow * 384 + ((ci ^ (nrow & 7)) << 4));
                        ldsm4(bfr[2 * nb2][0], bfr[2 * nb2][1],
                              bfr[2 * nb2 + 1][0], bfr[2 * nb2 + 1][1], addr);
                    }
#pragma unroll
                    for (int mi = 0; mi < 2; mi++) {
                        int r   = 32 * wm + 16 * mi + (lane & 7) + 8 * ((lane >> 3) & 1);
                        int cia = ki * 2 + (lane >> 4);
                        uint32_t addr = Ab + (uint32_t)(r * 128 + ((cia ^ (r & 7)) << 4));
                        uint32_t a[4];
                        ldsm4(a[0], a[1], a[2], a[3], addr);
#pragma unroll
                        for (int nb = 0; nb < 12; nb++)
                            mma16816(acc[mi][nb], a, bfr[nb]);
                    }
                }
            }
            __syncthreads();
        }

        // ---- epilogue: direct coalesced stores ----
        const int g  = lane >> 2;
        const int t4 = lane & 3;
#pragma unroll
        for (int mi = 0; mi < 2; mi++) {
#pragma unroll
            for (int half = 0; half < 2; half++) {
                int r    = 32 * wm + 16 * mi + 8 * half + g;
                int grow = t * 128 + r;
                if (grow < rows) {
                    unsigned gr   = (unsigned)grow;
                    unsigned node = row_to_node(gr, d);
                    unsigned sub  = gr - node * (unsigned)d;
                    float* po = out + (size_t)node * FEAT + segoff + sub * 192 +
                                96 * wn + t4 * 2;
#pragma unroll
                    for (int nb = 0; nb < 12; nb++) {
                        float2 v = make_float2(acc[mi][nb][2 * half],
                                               acc[mi][nb][2 * half + 1]);
                        *reinterpret_cast<float2*>(po + nb * 8) = v;
                    }
                }
            }
        }
    }
}

// ======================= launch =======================
extern "C" void kernel_launch(void* const* d_in, const int* in_sizes, int n_in,
                              void* d_out, int out_size) {
    const float* x  = (const float*)d_in[0];
    const float* Wb = (const float*)d_in[1];
    const float* WA = (const float*)d_in[2];
    const float* WB = (const float*)d_in[3];
    float* out = (float*)d_out;
    int n = in_sizes[0] / FEAT;

    static bool attr_set = false;
    if (!attr_set) {
        cudaFuncSetAttribute(lora_linear_main,
                             cudaFuncAttributeMaxDynamicSharedMemorySize, SMEM_TOTAL);
        attr_set = true;
    }

    prep_weights_kernel<<<(3 * MUL * MUL + 255) / 256, 256>>>(Wb, WA, WB);
    lora_linear_main<<<NCTA, 256, SMEM_TOTAL>>>(x, out, n);
}

// round 5
// speedup vs baseline: 1.4602x; 1.4602x over previous
#include <cuda_runtime.h>
#include <cuda_fp16.h>
#include <cstdint>

// ======================= problem constants =======================
static constexpr int MUL  = 192;
static constexpr int FEAT = 1728;

static constexpr int NCTA = 148;
static constexpr int C0 = 16, C1 = 49;       // C2 = 148-16-49 = 83

// SMEM layout (dynamic):
//  [0, 73728)        W  : 192 rows(n) x 384B (192 fp16), XOR-swizzled 16B chunks (ci ^ (n&7))
//  [73728, +3*32768) A  : 3 stages of fp32 x-chunk: 128 rows x 256B, chunk swizzle ci ^ (2*(r&7))
static constexpr int SM_W    = 0;
static constexpr int W_ONE   = 73728;
static constexpr int SM_A    = W_ONE;               // 73728
static constexpr int A_STAGE = 32768;
static constexpr int SMEM_TOTAL = SM_A + 3 * A_STAGE;  // 172032

// Folded weights, fp16, layout [k][o][m]  (B operand: n rows, k cols)
__device__ __align__(16) __half g_W[3 * MUL * MUL];

// ======================= prep: fold LoRA -> fp16 =======================
__global__ void prep_weights_kernel(const float* __restrict__ Wb,
                                    const float* __restrict__ WA,
                                    const float* __restrict__ WB) {
    int idx = blockIdx.x * blockDim.x + threadIdx.x;
    if (idx >= 3 * MUL * MUL) return;
    int k   = idx / (MUL * MUL);
    int rem = idx - k * (MUL * MUL);
    int o   = rem / MUL;            // output channel (n)
    int m   = rem - o * MUL;        // input channel  (k of GEMM)

    const float pw_base = rsqrtf(192.0f);
    const float pw_B    = rsqrtf(8.0f);

    float acc = 0.0f;
#pragma unroll
    for (int r = 0; r < 8; r++)
        acc += WA[(k * MUL + m) * 8 + r] * WB[(k * 8 + r) * MUL + o];
    float w = pw_base * Wb[(k * MUL + m) * MUL + o] + 2.0f * pw_base * pw_B * acc;

    g_W[idx] = __float2half_rn(w);   // [k][o][m]
}

// ======================= device helpers =======================
__device__ __forceinline__ uint32_t smem_to_u32(const void* p) {
    uint32_t a;
    asm("{ .reg .u64 t; cvta.to.shared.u64 t, %1; cvt.u32.u64 %0, t; }"
        : "=r"(a) : "l"(p));
    return a;
}

__device__ __forceinline__ unsigned row_to_node(unsigned g, int d) {
    if (d == 1) return g;
    if (d == 3) return __umulhi(g, 0xAAAAAAABu) >> 1;
    return __umulhi(g, 0xCCCCCCCDu) >> 2;   // d == 5
}

__device__ __forceinline__ void ldsm4(uint32_t& r0, uint32_t& r1,
                                      uint32_t& r2, uint32_t& r3, uint32_t addr) {
    asm volatile("ldmatrix.sync.aligned.m8n8.x4.shared.b16 {%0,%1,%2,%3}, [%4];"
                 : "=r"(r0), "=r"(r1), "=r"(r2), "=r"(r3) : "r"(addr));
}

__device__ __forceinline__ void mma16816(float c[4], const uint32_t a[4],
                                         const uint32_t b[2]) {
    asm volatile("mma.sync.aligned.m16n8k16.row.col.f32.f16.f16.f32 "
                 "{%0,%1,%2,%3}, {%4,%5,%6,%7}, {%8,%9}, {%0,%1,%2,%3};"
                 : "+f"(c[0]), "+f"(c[1]), "+f"(c[2]), "+f"(c[3])
                 : "r"(a[0]), "r"(a[1]), "r"(a[2]), "r"(a[3]),
                   "r"(b[0]), "r"(b[1]));
}

__device__ __forceinline__ float2 lds64(uint32_t addr) {
    float2 v;
    asm volatile("ld.shared.v2.f32 {%0,%1}, [%2];"
                 : "=f"(v.x), "=f"(v.y) : "r"(addr));
    return v;
}

// exact fp32 -> fp16 hi/lo split of a float pair; returns packed h2 (lo=a) and l2
__device__ __forceinline__ void split_h2(float a, float b, uint32_t& hp, uint32_t& lp) {
    __half2 h = __floats2half2_rn(a, b);
    float2  g = __half22float2(h);
    __half2 l = __floats2half2_rn(a - g.x, b - g.y);
    hp = *reinterpret_cast<uint32_t*>(&h);
    lp = *reinterpret_cast<uint32_t*>(&l);
}

// ======================= main kernel =======================
extern "C" __global__ void __launch_bounds__(256, 1)
lora_linear_main(const float* __restrict__ x, float* __restrict__ out, int n) {
    extern __shared__ char smem[];
    const uint32_t sb  = smem_to_u32(smem);
    const int tid  = threadIdx.x;
    const int lane = tid & 31;
    const int wid  = tid >> 5;
    const int wm   = wid & 3;       // warp M position (32 rows)
    const int wn   = wid >> 2;      // warp N position (96 cols)

    // ---- CTA -> (irrep, tile range) ----
    int b = blockIdx.x;
    int k, idx, nC;
    if (b < C0)            { k = 0; idx = b;            nC = C0; }
    else if (b < C0 + C1)  { k = 1; idx = b - C0;       nC = C1; }
    else                   { k = 2; idx = b - C0 - C1;  nC = NCTA - C0 - C1; }
    const int d      = (k == 0) ? 1 : (k == 1) ? 3 : 5;
    const int segoff = (k == 0) ? 0 : (k == 1) ? 192 : 768;
    const int rows   = n * d;
    const int T      = (rows + 127) >> 7;
    const int t0 = (int)(((long long)idx * T) / nC);
    const int t1 = (int)(((long long)(idx + 1) * T) / nC);
    const int C  = (t1 - t0) * 3;

    // ---- copy W into smem, XOR row-swizzle (16B chunk ci ^= (n & 7)) ----
    {
        const float4* gw = reinterpret_cast<const float4*>(g_W + (size_t)k * MUL * MUL);
        for (int i = tid; i < W_ONE / 16; i += 256) {   // 4608 chunks
            int nrow = i / 24;
            int ci   = i - nrow * 24;
            int dst  = nrow * 384 + (ci ^ (nrow & 7)) * 16;
            *reinterpret_cast<float4*>(smem + SM_W + dst) = gw[i];
        }
    }

    // ---- cp.async chunk issue (one commit group per chunk, always) ----
    auto issue_chunk = [&](int cc) {
        if (cc < C) {
            const int t     = t0 + cc / 3;
            const int c     = cc - 3 * (cc / 3);
            const int stage = cc % 3;
            const uint32_t sA = sb + (uint32_t)(SM_A + stage * A_STAGE);
#pragma unroll
            for (int q = 0; q < 8; q++) {
                int id  = tid + q * 256;      // 16B-chunk index, 0..2047
                int r   = id >> 4;            // row in tile
                int ci  = id & 15;
                int grow = t * 128 + r;
                int ok   = grow < rows;
                unsigned gr   = (unsigned)(ok ? grow : 0);
                unsigned node = row_to_node(gr, d);
                unsigned sub  = gr - node * (unsigned)d;
                const float* src = x + (size_t)node * FEAT + segoff + sub * 192 +
                                   c * 64 + ci * 4;
                uint32_t dst = sA + (uint32_t)(r * 256 + ((ci ^ (2 * (r & 7))) & 15) * 16);
                int sz = ok ? 16 : 0;
                asm volatile("cp.async.cg.shared.global [%0], [%1], 16, %2;"
                             :: "r"(dst), "l"(src), "r"(sz) : "memory");
            }
        }
        asm volatile("cp.async.commit_group;" ::: "memory");
    };

    // prologue: 3 stages in flight
    issue_chunk(0);
    issue_chunk(1);
    issue_chunk(2);

    float acc[2][12][4];
    const uint32_t Wm = sb + (uint32_t)SM_W;

    for (int cc = 0; cc < C; ++cc) {
        const int t = t0 + cc / 3;
        const int c = cc - 3 * (cc / 3);
        const int stage = cc % 3;
        const uint32_t sA = sb + (uint32_t)(SM_A + stage * A_STAGE);

        asm volatile("cp.async.wait_group 2;" ::: "memory");
        __syncthreads();

        if (c == 0) {
#pragma unroll
            for (int mi = 0; mi < 2; mi++)
#pragma unroll
                for (int nb = 0; nb < 12; nb++)
#pragma unroll
                    for (int j = 0; j < 4; j++) acc[mi][nb][j] = 0.0f;
        }

        // ---- MMA over this 64-col chunk ----
#pragma unroll
        for (int ki = 0; ki < 4; ki++) {
            // B fragments: 96 cols for this warp, 16-k slice
            const int cib = c * 8 + ki * 2;
            uint32_t bfr[12][2];
#pragma unroll
            for (int nb2 = 0; nb2 < 6; nb2++) {
                int nrow = 96 * wn + nb2 * 16 + 8 * (lane >> 4) + (lane & 7);
                int ci   = cib + ((lane >> 3) & 1);
                uint32_t addr = Wm + (uint32_t)(nrow * 384 + ((ci ^ (nrow & 7)) << 4));
                ldsm4(bfr[2 * nb2][0], bfr[2 * nb2][1],
                      bfr[2 * nb2 + 1][0], bfr[2 * nb2 + 1][1], addr);
            }
#pragma unroll
            for (int mi = 0; mi < 2; mi++) {
                // A fragment straight from fp32 staging: 4x LDS.64 + exact hi/lo split
                const int rA = 32 * wm + 16 * mi + (lane >> 2);
                const int cq = lane & 3;               // col pair (cq*2, cq*2+1)
                const int ciA = ki * 4 + (cq >> 1);    // 16B chunk in row
                const int ib  = (cq & 1) * 8;          // byte within chunk
                auto aaddr = [&](int r, int cio) {
                    return sA + (uint32_t)(r * 256 + ((( (ciA + cio) ^ (2 * (r & 7))) & 15) << 4) + ib);
                };
                float2 f0 = lds64(aaddr(rA,     0));
                float2 f1 = lds64(aaddr(rA + 8, 0));
                float2 f2 = lds64(aaddr(rA,     2));
                float2 f3 = lds64(aaddr(rA + 8, 2));
                uint32_t ah[4], al[4];
                split_h2(f0.x, f0.y, ah[0], al[0]);
                split_h2(f1.x, f1.y, ah[1], al[1]);
                split_h2(f2.x, f2.y, ah[2], al[2]);
                split_h2(f3.x, f3.y, ah[3], al[3]);
#pragma unroll
                for (int nb = 0; nb < 12; nb++) mma16816(acc[mi][nb], ah, bfr[nb]);
#pragma unroll
                for (int nb = 0; nb < 12; nb++) mma16816(acc[mi][nb], al, bfr[nb]);
            }
        }

        // ---- epilogue on last chunk of tile ----
        if (c == 2) {
            const int g  = lane >> 2;
            const int t4 = lane & 3;
#pragma unroll
            for (int mi = 0; mi < 2; mi++) {
#pragma unroll
                for (int half = 0; half < 2; half++) {
                    int r    = 32 * wm + 16 * mi + 8 * half + g;
                    int grow = t * 128 + r;
                    if (grow < rows) {
                        unsigned gr   = (unsigned)grow;
                        unsigned node = row_to_node(gr, d);
                        unsigned sub  = gr - node * (unsigned)d;
                        float* po = out + (size_t)node * FEAT + segoff + sub * 192 +
                                    96 * wn + t4 * 2;
#pragma unroll
                        for (int nb = 0; nb < 12; nb++) {
                            float2 v = make_float2(acc[mi][nb][2 * half],
                                                   acc[mi][nb][2 * half + 1]);
                            *reinterpret_cast<float2*>(po + nb * 8) = v;
                        }
                    }
                }
            }
        }

        __syncthreads();          // all warps done reading this stage
        issue_chunk(cc + 3);      // refill stage
    }
}

// ======================= launch =======================
extern "C" void kernel_launch(void* const* d_in, const int* in_sizes, int n_in,
                              void* d_out, int out_size) {
    const float* x  = (const float*)d_in[0];
    const float* Wb = (const float*)d_in[1];
    const float* WA = (const float*)d_in[2];
    const float* WB = (const float*)d_in[3];
    float* out = (float*)d_out;
    int n = in_sizes[0] / FEAT;

    static bool attr_set = false;
    if (!attr_set) {
        cudaFuncSetAttribute(lora_linear_main,
                             cudaFuncAttributeMaxDynamicSharedMemorySize, SMEM_TOTAL);
        attr_set = true;
    }

    prep_weights_kernel<<<(3 * MUL * MUL + 255) / 256, 256>>>(Wb, WA, WB);
    lora_linear_main<<<NCTA, 256, SMEM_TOTAL>>>(x, out, n);
}

// round 6
// speedup vs baseline: 1.9809x; 1.3566x over previous
#include <cuda_runtime.h>
#include <cuda_fp16.h>
#include <cstdint>

// ======================= problem constants =======================
static constexpr int MUL  = 192;
static constexpr int FEAT = 1728;

static constexpr int NCTA = 148;
static constexpr int C0 = 16, C1 = 49;       // C2 = 148-16-49 = 83

// SMEM layout (dynamic):
//  [0, 73728)        W  : 192 rows(n) x 384B (192 fp16), XOR-swizzled 16B chunks (ci ^ (n&7))
//  [73728, +3*32768) A  : 3 stages of fp32 x-chunk: 128 rows x 256B, chunk swizzle ci ^ (2*(r&7))
static constexpr int SM_W    = 0;
static constexpr int W_ONE   = 73728;
static constexpr int SM_A    = W_ONE;               // 73728
static constexpr int A_STAGE = 32768;
static constexpr int SMEM_TOTAL = SM_A + 3 * A_STAGE;  // 172032

static constexpr int NTHR = 512;

// Folded weights, fp16, layout [k][o][m]  (B operand: n rows, k cols)
__device__ __align__(16) __half g_W[3 * MUL * MUL];

// ======================= prep: fold LoRA -> fp16 =======================
__global__ void prep_weights_kernel(const float* __restrict__ Wb,
                                    const float* __restrict__ WA,
                                    const float* __restrict__ WB) {
    int idx = blockIdx.x * blockDim.x + threadIdx.x;
    if (idx >= 3 * MUL * MUL) return;
    int k   = idx / (MUL * MUL);
    int rem = idx - k * (MUL * MUL);
    int o   = rem / MUL;            // output channel (n)
    int m   = rem - o * MUL;        // input channel  (k of GEMM)

    const float pw_base = rsqrtf(192.0f);
    const float pw_B    = rsqrtf(8.0f);

    float acc = 0.0f;
#pragma unroll
    for (int r = 0; r < 8; r++)
        acc += WA[(k * MUL + m) * 8 + r] * WB[(k * 8 + r) * MUL + o];
    float w = pw_base * Wb[(k * MUL + m) * MUL + o] + 2.0f * pw_base * pw_B * acc;

    g_W[idx] = __float2half_rn(w);   // [k][o][m]
}

// ======================= device helpers =======================
__device__ __forceinline__ uint32_t smem_to_u32(const void* p) {
    uint32_t a;
    asm("{ .reg .u64 t; cvta.to.shared.u64 t, %1; cvt.u32.u64 %0, t; }"
        : "=r"(a) : "l"(p));
    return a;
}

__device__ __forceinline__ unsigned row_to_node(unsigned g, int d) {
    if (d == 1) return g;
    if (d == 3) return __umulhi(g, 0xAAAAAAABu) >> 1;
    return __umulhi(g, 0xCCCCCCCDu) >> 2;   // d == 5
}

__device__ __forceinline__ void ldsm4(uint32_t& r0, uint32_t& r1,
                                      uint32_t& r2, uint32_t& r3, uint32_t addr) {
    asm volatile("ldmatrix.sync.aligned.m8n8.x4.shared.b16 {%0,%1,%2,%3}, [%4];"
                 : "=r"(r0), "=r"(r1), "=r"(r2), "=r"(r3) : "r"(addr));
}

__device__ __forceinline__ void mma16816(float c[4], const uint32_t a[4],
                                         const uint32_t b[2]) {
    asm volatile("mma.sync.aligned.m16n8k16.row.col.f32.f16.f16.f32 "
                 "{%0,%1,%2,%3}, {%4,%5,%6,%7}, {%8,%9}, {%0,%1,%2,%3};"
                 : "+f"(c[0]), "+f"(c[1]), "+f"(c[2]), "+f"(c[3])
                 : "r"(a[0]), "r"(a[1]), "r"(a[2]), "r"(a[3]),
                   "r"(b[0]), "r"(b[1]));
}

__device__ __forceinline__ float2 lds64(uint32_t addr) {
    float2 v;
    asm volatile("ld.shared.v2.f32 {%0,%1}, [%2];"
                 : "=f"(v.x), "=f"(v.y) : "r"(addr));
    return v;
}

__device__ __forceinline__ uint32_t cvt_h2(float a, float b) {
    __half2 h = __floats2half2_rn(a, b);
    return *reinterpret_cast<uint32_t*>(&h);
}

// ======================= main kernel =======================
extern "C" __global__ void __launch_bounds__(NTHR, 1)
lora_linear_main(const float* __restrict__ x, float* __restrict__ out, int n) {
    extern __shared__ char smem[];
    const uint32_t sb  = smem_to_u32(smem);
    const int tid  = threadIdx.x;
    const int lane = tid & 31;
    const int wid  = tid >> 5;
    const int wm   = wid & 3;       // warp M position (32 rows of 128)
    const int wn   = wid >> 2;      // warp N position (48 cols of 192), 0..3

    // ---- CTA -> (irrep, tile range) ----
    int b = blockIdx.x;
    int k, idx, nC;
    if (b < C0)            { k = 0; idx = b;            nC = C0; }
    else if (b < C0 + C1)  { k = 1; idx = b - C0;       nC = C1; }
    else                   { k = 2; idx = b - C0 - C1;  nC = NCTA - C0 - C1; }
    const int d      = (k == 0) ? 1 : (k == 1) ? 3 : 5;
    const int segoff = (k == 0) ? 0 : (k == 1) ? 192 : 768;
    const int rows   = n * d;
    const int T      = (rows + 127) >> 7;
    const int t0 = (int)(((long long)idx * T) / nC);
    const int t1 = (int)(((long long)(idx + 1) * T) / nC);
    const int C  = (t1 - t0) * 3;

    // ---- copy W into smem, XOR row-swizzle (16B chunk ci ^= (n & 7)) ----
    {
        const float4* gw = reinterpret_cast<const float4*>(g_W + (size_t)k * MUL * MUL);
        for (int i = tid; i < W_ONE / 16; i += NTHR) {   // 4608 chunks
            int nrow = i / 24;
            int ci   = i - nrow * 24;
            int dst  = nrow * 384 + (ci ^ (nrow & 7)) * 16;
            *reinterpret_cast<float4*>(smem + SM_W + dst) = gw[i];
        }
    }

    // ---- cp.async chunk issue (one commit group per chunk, always) ----
    auto issue_chunk = [&](int cc) {
        if (cc < C) {
            const int t     = t0 + cc / 3;
            const int c     = cc - 3 * (cc / 3);
            const int stage = cc % 3;
            const uint32_t sA = sb + (uint32_t)(SM_A + stage * A_STAGE);
#pragma unroll
            for (int q = 0; q < 4; q++) {
                int id  = tid + q * NTHR;     // 16B-chunk index, 0..2047
                int r   = id >> 4;            // row in tile
                int ci  = id & 15;
                int grow = t * 128 + r;
                int ok   = grow < rows;
                unsigned gr   = (unsigned)(ok ? grow : 0);
                unsigned node = row_to_node(gr, d);
                unsigned sub  = gr - node * (unsigned)d;
                const float* src = x + (size_t)node * FEAT + segoff + sub * 192 +
                                   c * 64 + ci * 4;
                uint32_t dst = sA + (uint32_t)(r * 256 + ((ci ^ (2 * (r & 7))) & 15) * 16);
                int sz = ok ? 16 : 0;
                asm volatile("cp.async.cg.shared.global [%0], [%1], 16, %2;"
                             :: "r"(dst), "l"(src), "r"(sz) : "memory");
            }
        }
        asm volatile("cp.async.commit_group;" ::: "memory");
    };

    // prologue: 3 stages in flight
    issue_chunk(0);
    issue_chunk(1);
    issue_chunk(2);

    float acc[2][6][4];
    const uint32_t Wm = sb + (uint32_t)SM_W;

    for (int cc = 0; cc < C; ++cc) {
        const int t = t0 + cc / 3;
        const int c = cc - 3 * (cc / 3);
        const int stage = cc % 3;
        const uint32_t sA = sb + (uint32_t)(SM_A + stage * A_STAGE);

        asm volatile("cp.async.wait_group 2;" ::: "memory");
        __syncthreads();

        if (c == 0) {
#pragma unroll
            for (int mi = 0; mi < 2; mi++)
#pragma unroll
                for (int nb = 0; nb < 6; nb++)
#pragma unroll
                    for (int j = 0; j < 4; j++) acc[mi][nb][j] = 0.0f;
        }

        // ---- MMA over this 64-col chunk ----
#pragma unroll
        for (int ki = 0; ki < 4; ki++) {
            // B fragments: 48 cols for this warp, 16-k slice
            const int cib = c * 8 + ki * 2;
            uint32_t bfr[6][2];
#pragma unroll
            for (int nb2 = 0; nb2 < 3; nb2++) {
                int nrow = 48 * wn + nb2 * 16 + 8 * (lane >> 4) + (lane & 7);
                int ci   = cib + ((lane >> 3) & 1);
                uint32_t addr = Wm + (uint32_t)(nrow * 384 + ((ci ^ (nrow & 7)) << 4));
                ldsm4(bfr[2 * nb2][0], bfr[2 * nb2][1],
                      bfr[2 * nb2 + 1][0], bfr[2 * nb2 + 1][1], addr);
            }
#pragma unroll
            for (int mi = 0; mi < 2; mi++) {
                // A fragment straight from fp32 staging: 4x LDS.64 + fp16 convert
                const int rA = 32 * wm + 16 * mi + (lane >> 2);
                const int cq = lane & 3;               // col pair (cq*2, cq*2+1)
                const int ciA = ki * 4 + (cq >> 1);    // 16B chunk in row
                const int ib  = (cq & 1) * 8;          // byte within chunk
                auto aaddr = [&](int r, int cio) {
                    return sA + (uint32_t)(r * 256 +
                           ((((ciA + cio) ^ (2 * (r & 7))) & 15) << 4) + ib);
                };
                float2 f0 = lds64(aaddr(rA,     0));
                float2 f1 = lds64(aaddr(rA + 8, 0));
                float2 f2 = lds64(aaddr(rA,     2));
                float2 f3 = lds64(aaddr(rA + 8, 2));
                uint32_t ah[4];
                ah[0] = cvt_h2(f0.x, f0.y);
                ah[1] = cvt_h2(f1.x, f1.y);
                ah[2] = cvt_h2(f2.x, f2.y);
                ah[3] = cvt_h2(f3.x, f3.y);
#pragma unroll
                for (int nb = 0; nb < 6; nb++) mma16816(acc[mi][nb], ah, bfr[nb]);
            }
        }

        // ---- epilogue on last chunk of tile ----
        if (c == 2) {
            const int g  = lane >> 2;
            const int t4 = lane & 3;
#pragma unroll
            for (int mi = 0; mi < 2; mi++) {
#pragma unroll
                for (int half = 0; half < 2; half++) {
                    int r    = 32 * wm + 16 * mi + 8 * half + g;
                    int grow = t * 128 + r;
                    if (grow < rows) {
                        unsigned gr   = (unsigned)grow;
                        unsigned node = row_to_node(gr, d);
                        unsigned sub  = gr - node * (unsigned)d;
                        float* po = out + (size_t)node * FEAT + segoff + sub * 192 +
                                    48 * wn + t4 * 2;
#pragma unroll
                        for (int nb = 0; nb < 6; nb++) {
                            float2 v = make_float2(acc[mi][nb][2 * half],
                                                   acc[mi][nb][2 * half + 1]);
                            *reinterpret_cast<float2*>(po + nb * 8) = v;
                        }
                    }
                }
            }
        }

        __syncthreads();          // all warps done reading this stage
        issue_chunk(cc + 3);      // refill stage
    }
}

// ======================= launch =======================
extern "C" void kernel_launch(void* const* d_in, const int* in_sizes, int n_in,
                              void* d_out, int out_size) {
    const float* x  = (const float*)d_in[0];
    const float* Wb = (const float*)d_in[1];
    const float* WA = (const float*)d_in[2];
    const float* WB = (const float*)d_in[3];
    float* out = (float*)d_out;
    int n = in_sizes[0] / FEAT;

    static bool attr_set = false;
    if (!attr_set) {
        cudaFuncSetAttribute(lora_linear_main,
                             cudaFuncAttributeMaxDynamicSharedMemorySize, SMEM_TOTAL);
        attr_set = true;
    }

    prep_weights_kernel<<<(3 * MUL * MUL + 255) / 256, 256>>>(Wb, WA, WB);
    lora_linear_main<<<NCTA, NTHR, SMEM_TOTAL>>>(x, out, n);
}

// round 7
// speedup vs baseline: 2.0482x; 1.0340x over previous
#include <cuda_runtime.h>
#include <cuda_fp16.h>
#include <cstdint>

// ======================= problem constants =======================
static constexpr int MUL  = 192;
static constexpr int FEAT = 1728;

static constexpr int NCTA = 148;
static constexpr int C0 = 16, C1 = 49;       // C2 = 148-16-49 = 83

// SMEM layout (dynamic):
//  [0, 73728)        W : 192 rows(n) x 384B (192 fp16), XOR-swizzled 16B chunks (ci ^ (n&7))
//  [73728, +2*16384) A : 2 stages of fp16 x-chunk: 128 rows x 128B, swizzle (ci ^ (r&7))
static constexpr int SM_W    = 0;
static constexpr int W_ONE   = 73728;
static constexpr int SM_A    = W_ONE;                  // 73728
static constexpr int A_STAGE = 16384;
static constexpr int SMEM_TOTAL = SM_A + 2 * A_STAGE;  // 106496

static constexpr int NTHR = 512;

// Folded weights, fp16, layout [k][o][m]  (B operand: n rows, k cols)
__device__ __align__(16) __half g_W[3 * MUL * MUL];

// ======================= prep: fold LoRA -> fp16 =======================
__global__ void prep_weights_kernel(const float* __restrict__ Wb,
                                    const float* __restrict__ WA,
                                    const float* __restrict__ WB) {
    int idx = blockIdx.x * blockDim.x + threadIdx.x;
    if (idx >= 3 * MUL * MUL) return;
    int k   = idx / (MUL * MUL);
    int rem = idx - k * (MUL * MUL);
    int o   = rem / MUL;            // output channel (n)
    int m   = rem - o * MUL;        // input channel  (k of GEMM)

    const float pw_base = rsqrtf(192.0f);
    const float pw_B    = rsqrtf(8.0f);

    float acc = 0.0f;
#pragma unroll
    for (int r = 0; r < 8; r++)
        acc += WA[(k * MUL + m) * 8 + r] * WB[(k * 8 + r) * MUL + o];
    float w = pw_base * Wb[(k * MUL + m) * MUL + o] + 2.0f * pw_base * pw_B * acc;

    g_W[idx] = __float2half_rn(w);   // [k][o][m]
}

// ======================= device helpers =======================
__device__ __forceinline__ uint32_t smem_to_u32(const void* p) {
    uint32_t a;
    asm("{ .reg .u64 t; cvta.to.shared.u64 t, %1; cvt.u32.u64 %0, t; }"
        : "=r"(a) : "l"(p));
    return a;
}

__device__ __forceinline__ unsigned row_to_node(unsigned g, int d) {
    if (d == 1) return g;
    if (d == 3) return __umulhi(g, 0xAAAAAAABu) >> 1;
    return __umulhi(g, 0xCCCCCCCDu) >> 2;   // d == 5
}

__device__ __forceinline__ void ldsm4(uint32_t& r0, uint32_t& r1,
                                      uint32_t& r2, uint32_t& r3, uint32_t addr) {
    asm volatile("ldmatrix.sync.aligned.m8n8.x4.shared.b16 {%0,%1,%2,%3}, [%4];"
                 : "=r"(r0), "=r"(r1), "=r"(r2), "=r"(r3) : "r"(addr));
}

__device__ __forceinline__ void mma16816(float c[4], const uint32_t a[4],
                                         const uint32_t b[2]) {
    asm volatile("mma.sync.aligned.m16n8k16.row.col.f32.f16.f16.f32 "
                 "{%0,%1,%2,%3}, {%4,%5,%6,%7}, {%8,%9}, {%0,%1,%2,%3};"
                 : "+f"(c[0]), "+f"(c[1]), "+f"(c[2]), "+f"(c[3])
                 : "r"(a[0]), "r"(a[1]), "r"(a[2]), "r"(a[3]),
                   "r"(b[0]), "r"(b[1]));
}

__device__ __forceinline__ uint32_t cvt_h2(float a, float b) {
    __half2 h = __floats2half2_rn(a, b);
    return *reinterpret_cast<uint32_t*>(&h);
}

// ======================= main kernel =======================
extern "C" __global__ void __launch_bounds__(NTHR, 1)
lora_linear_main(const float* __restrict__ x, float* __restrict__ out, int n) {
    extern __shared__ char smem[];
    const uint32_t sb  = smem_to_u32(smem);
    const int tid  = threadIdx.x;
    const int lane = tid & 31;
    const int wid  = tid >> 5;
    const int wm   = wid & 3;       // warp M position (32 rows of 128)
    const int wn   = wid >> 2;      // warp N position (48 cols of 192), 0..3

    // ---- CTA -> (irrep, tile range) ----
    int b = blockIdx.x;
    int k, idx, nC;
    if (b < C0)            { k = 0; idx = b;            nC = C0; }
    else if (b < C0 + C1)  { k = 1; idx = b - C0;       nC = C1; }
    else                   { k = 2; idx = b - C0 - C1;  nC = NCTA - C0 - C1; }
    const int d      = (k == 0) ? 1 : (k == 1) ? 3 : 5;
    const int segoff = (k == 0) ? 0 : (k == 1) ? 192 : 768;
    const int rows   = n * d;
    const int T      = (rows + 127) >> 7;
    const int t0 = (int)(((long long)idx * T) / nC);
    const int t1 = (int)(((long long)(idx + 1) * T) / nC);
    const int C  = (t1 - t0) * 3;

    // ---- copy W into smem, XOR row-swizzle (16B chunk ci ^= (n & 7)) ----
    {
        const float4* gw = reinterpret_cast<const float4*>(g_W + (size_t)k * MUL * MUL);
        for (int i = tid; i < W_ONE / 16; i += NTHR) {   // 4608 chunks
            int nrow = i / 24;
            int ci   = i - nrow * 24;
            int dst  = nrow * 384 + (ci ^ (nrow & 7)) * 16;
            *reinterpret_cast<float4*>(smem + SM_W + dst) = gw[i];
        }
    }

    // ---- per-thread x-load geometry (fixed rows/cols per thread) ----
    // id = tid + q*512 indexes the 2048 float4s of a 128x64 fp32 chunk
    int rq[4], cq[4];
#pragma unroll
    for (int q = 0; q < 4; q++) { rq[q] = (tid + q * NTHR) >> 4; cq[q] = (tid + q * NTHR) & 15; }

    const float* pb[4];
    bool pok[4];
    auto comp_base = [&](int t) {
#pragma unroll
        for (int q = 0; q < 4; q++) {
            int grow = t * 128 + rq[q];
            pok[q] = grow < rows;
            unsigned gr   = (unsigned)(pok[q] ? grow : 0);
            unsigned node = row_to_node(gr, d);
            unsigned sub  = gr - node * (unsigned)d;
            pb[q] = x + (size_t)node * FEAT + segoff + sub * 192 + cq[q] * 4;
        }
    };

    float4 pf[4];
    auto ldg_pf = [&](int c) {
#pragma unroll
        for (int q = 0; q < 4; q++) {
            float4 v = make_float4(0.f, 0.f, 0.f, 0.f);
            if (pok[q]) v = *reinterpret_cast<const float4*>(pb[q] + c * 64);
            pf[q] = v;
        }
    };

    if (C > 0) { comp_base(t0); ldg_pf(0); }

    float acc[2][6][4];
    const uint32_t Wm = sb + (uint32_t)SM_W;

    for (int cc = 0; cc < C; ++cc) {
        const int t = t0 + cc / 3;
        const int c = cc - 3 * (cc / 3);
        const uint32_t sA = sb + (uint32_t)(SM_A + (cc & 1) * A_STAGE);

        // ---- STS: convert pf -> fp16 staged (swizzled for ldmatrix) ----
#pragma unroll
        for (int q = 0; q < 4; q++) {
            uint32_t u0 = cvt_h2(pf[q].x, pf[q].y);
            uint32_t u1 = cvt_h2(pf[q].z, pf[q].w);
            int r  = rq[q], ci = cq[q];
            uint32_t off = (uint32_t)(r * 128 + (((ci >> 1) ^ (r & 7)) << 4) +
                                      ((ci & 1) << 3));
            asm volatile("st.shared.v2.b32 [%0], {%1,%2};"
                         :: "r"(sA + off), "r"(u0), "r"(u1) : "memory");
        }
        __syncthreads();

        // ---- prefetch next chunk (flies during MMA below) ----
        {
            int nc2 = cc + 1;
            if (nc2 < C) {
                int c2 = nc2 - 3 * (nc2 / 3);
                if (c2 == 0) comp_base(t + 1);
                ldg_pf(c2);
            }
        }

        if (c == 0) {
#pragma unroll
            for (int mi = 0; mi < 2; mi++)
#pragma unroll
                for (int nb = 0; nb < 6; nb++)
#pragma unroll
                    for (int j = 0; j < 4; j++) acc[mi][nb][j] = 0.0f;
        }

        // ---- MMA over this 64-col chunk ----
#pragma unroll
        for (int ki = 0; ki < 4; ki++) {
            // B fragments: 48 cols for this warp, 16-k slice
            const int cib = c * 8 + ki * 2;
            uint32_t bfr[6][2];
#pragma unroll
            for (int nb2 = 0; nb2 < 3; nb2++) {
                int nrow = 48 * wn + nb2 * 16 + 8 * (lane >> 4) + (lane & 7);
                int ci   = cib + ((lane >> 3) & 1);
                uint32_t addr = Wm + (uint32_t)(nrow * 384 + ((ci ^ (nrow & 7)) << 4));
                ldsm4(bfr[2 * nb2][0], bfr[2 * nb2][1],
                      bfr[2 * nb2 + 1][0], bfr[2 * nb2 + 1][1], addr);
            }
#pragma unroll
            for (int mi = 0; mi < 2; mi++) {
                // A fragment via ldmatrix from fp16 staging
                int rA  = 32 * wm + 16 * mi + (lane & 7) + 8 * ((lane >> 3) & 1);
                int cia = ki * 2 + (lane >> 4);
                uint32_t addr = sA + (uint32_t)(rA * 128 + ((cia ^ (rA & 7)) << 4));
                uint32_t a[4];
                ldsm4(a[0], a[1], a[2], a[3], addr);
#pragma unroll
                for (int nb = 0; nb < 6; nb++) mma16816(acc[mi][nb], a, bfr[nb]);
            }
        }

        // ---- epilogue on last chunk of tile ----
        if (c == 2) {
            const int g  = lane >> 2;
            const int t4 = lane & 3;
#pragma unroll
            for (int mi = 0; mi < 2; mi++) {
#pragma unroll
                for (int half = 0; half < 2; half++) {
                    int r    = 32 * wm + 16 * mi + 8 * half + g;
                    int grow = t * 128 + r;
                    if (grow < rows) {
                        unsigned gr   = (unsigned)grow;
                        unsigned node = row_to_node(gr, d);
                        unsigned sub  = gr - node * (unsigned)d;
                        float* po = out + (size_t)node * FEAT + segoff + sub * 192 +
                                    48 * wn + t4 * 2;
#pragma unroll
                        for (int nb = 0; nb < 6; nb++) {
                            float2 v = make_float2(acc[mi][nb][2 * half],
                                                   acc[mi][nb][2 * half + 1]);
                            *reinterpret_cast<float2*>(po + nb * 8) = v;
                        }
                    }
                }
            }
        }
    }
}

// ======================= launch =======================
extern "C" void kernel_launch(void* const* d_in, const int* in_sizes, int n_in,
                              void* d_out, int out_size) {
    const float* x  = (const float*)d_in[0];
    const float* Wb = (const float*)d_in[1];
    const float* WA = (const float*)d_in[2];
    const float* WB = (const float*)d_in[3];
    float* out = (float*)d_out;
    int n = in_sizes[0] / FEAT;

    static bool attr_set = false;
    if (!attr_set) {
        cudaFuncSetAttribute(lora_linear_main,
                             cudaFuncAttributeMaxDynamicSharedMemorySize, SMEM_TOTAL);
        attr_set = true;
    }

    prep_weights_kernel<<<(3 * MUL * MUL + 255) / 256, 256>>>(Wb, WA, WB);
    lora_linear_main<<<NCTA, NTHR, SMEM_TOTAL>>>(x, out, n);
}

// round 8
// speedup vs baseline: 2.1537x; 1.0515x over previous
#include <cuda_runtime.h>
#include <cuda_fp16.h>
#include <cstdint>

// ======================= problem constants =======================
static constexpr int MUL  = 192;
static constexpr int FEAT = 1728;

static constexpr int NCTA = 296;              // 2 CTAs per SM
static constexpr int C0 = 32, C1 = 98;        // C2 = 296-32-98 = 166

// SMEM layout (dynamic):
//  [0, 73728)       W : 192 rows(n) x 384B (192 fp16), XOR-swizzled 16B chunks (ci ^ (n&7))
//  [73728, +2*8192) A : 2 stages of fp16 x-chunk: 64 rows x 128B, swizzle (ci ^ (r&7))
static constexpr int SM_W    = 0;
static constexpr int W_ONE   = 73728;
static constexpr int SM_A    = W_ONE;                  // 73728
static constexpr int A_STAGE = 8192;
static constexpr int SMEM_TOTAL = SM_A + 2 * A_STAGE;  // 90112

static constexpr int NTHR = 256;
static constexpr int TILE_M = 64;

// Folded weights, fp16, layout [k][o][m]  (B operand: n rows, k cols)
__device__ __align__(16) __half g_W[3 * MUL * MUL];

// ======================= prep: fold LoRA -> fp16 =======================
__global__ void prep_weights_kernel(const float* __restrict__ Wb,
                                    const float* __restrict__ WA,
                                    const float* __restrict__ WB) {
    int idx = blockIdx.x * blockDim.x + threadIdx.x;
    if (idx >= 3 * MUL * MUL) return;
    int k   = idx / (MUL * MUL);
    int rem = idx - k * (MUL * MUL);
    int o   = rem / MUL;            // output channel (n)
    int m   = rem - o * MUL;        // input channel  (k of GEMM)

    const float pw_base = rsqrtf(192.0f);
    const float pw_B    = rsqrtf(8.0f);

    float acc = 0.0f;
#pragma unroll
    for (int r = 0; r < 8; r++)
        acc += WA[(k * MUL + m) * 8 + r] * WB[(k * 8 + r) * MUL + o];
    float w = pw_base * Wb[(k * MUL + m) * MUL + o] + 2.0f * pw_base * pw_B * acc;

    g_W[idx] = __float2half_rn(w);   // [k][o][m]
}

// ======================= device helpers =======================
__device__ __forceinline__ uint32_t smem_to_u32(const void* p) {
    uint32_t a;
    asm("{ .reg .u64 t; cvta.to.shared.u64 t, %1; cvt.u32.u64 %0, t; }"
        : "=r"(a) : "l"(p));
    return a;
}

__device__ __forceinline__ unsigned row_to_node(unsigned g, int d) {
    if (d == 1) return g;
    if (d == 3) return __umulhi(g, 0xAAAAAAABu) >> 1;
    return __umulhi(g, 0xCCCCCCCDu) >> 2;   // d == 5
}

__device__ __forceinline__ void ldsm4(uint32_t& r0, uint32_t& r1,
                                      uint32_t& r2, uint32_t& r3, uint32_t addr) {
    asm volatile("ldmatrix.sync.aligned.m8n8.x4.shared.b16 {%0,%1,%2,%3}, [%4];"
                 : "=r"(r0), "=r"(r1), "=r"(r2), "=r"(r3) : "r"(addr));
}

__device__ __forceinline__ void mma16816(float c[4], const uint32_t a[4],
                                         const uint32_t b[2]) {
    asm volatile("mma.sync.aligned.m16n8k16.row.col.f32.f16.f16.f32 "
                 "{%0,%1,%2,%3}, {%4,%5,%6,%7}, {%8,%9}, {%0,%1,%2,%3};"
                 : "+f"(c[0]), "+f"(c[1]), "+f"(c[2]), "+f"(c[3])
                 : "r"(a[0]), "r"(a[1]), "r"(a[2]), "r"(a[3]),
                   "r"(b[0]), "r"(b[1]));
}

__device__ __forceinline__ uint32_t cvt_h2(float a, float b) {
    __half2 h = __floats2half2_rn(a, b);
    return *reinterpret_cast<uint32_t*>(&h);
}

// ======================= main kernel =======================
extern "C" __global__ void __launch_bounds__(NTHR, 2)
lora_linear_main(const float* __restrict__ x, float* __restrict__ out, int n) {
    extern __shared__ char smem[];
    const uint32_t sb  = smem_to_u32(smem);
    const int tid  = threadIdx.x;
    const int lane = tid & 31;
    const int wid  = tid >> 5;
    const int wm   = wid & 1;       // warp M position (32 rows of 64)
    const int wn   = wid >> 1;      // warp N position (48 cols of 192), 0..3

    // ---- CTA -> (irrep, tile range) ----
    int b = blockIdx.x;
    int k, idx, nC;
    if (b < C0)            { k = 0; idx = b;            nC = C0; }
    else if (b < C0 + C1)  { k = 1; idx = b - C0;       nC = C1; }
    else                   { k = 2; idx = b - C0 - C1;  nC = NCTA - C0 - C1; }
    const int d      = (k == 0) ? 1 : (k == 1) ? 3 : 5;
    const int segoff = (k == 0) ? 0 : (k == 1) ? 192 : 768;
    const int rows   = n * d;
    const int T      = (rows + TILE_M - 1) / TILE_M;
    const int t0 = (int)(((long long)idx * T) / nC);
    const int t1 = (int)(((long long)(idx + 1) * T) / nC);
    const int C  = (t1 - t0) * 3;

    // ---- copy W into smem, XOR row-swizzle (16B chunk ci ^= (n & 7)) ----
    {
        const float4* gw = reinterpret_cast<const float4*>(g_W + (size_t)k * MUL * MUL);
        for (int i = tid; i < W_ONE / 16; i += NTHR) {   // 4608 chunks
            int nrow = i / 24;
            int ci   = i - nrow * 24;
            int dst  = nrow * 384 + (ci ^ (nrow & 7)) * 16;
            *reinterpret_cast<float4*>(smem + SM_W + dst) = gw[i];
        }
    }

    // ---- per-thread x-load geometry: 64 rows x 16 float4 per chunk ----
    int rq[4], cq[4];
#pragma unroll
    for (int q = 0; q < 4; q++) { rq[q] = (tid + q * NTHR) >> 4; cq[q] = (tid + q * NTHR) & 15; }

    const float* pb[4];
    bool pok[4];
    auto comp_base = [&](int t) {
#pragma unroll
        for (int q = 0; q < 4; q++) {
            int grow = t * TILE_M + rq[q];
            pok[q] = grow < rows;
            unsigned gr   = (unsigned)(pok[q] ? grow : 0);
            unsigned node = row_to_node(gr, d);
            unsigned sub  = gr - node * (unsigned)d;
            pb[q] = x + (size_t)node * FEAT + segoff + sub * 192 + cq[q] * 4;
        }
    };

    float4 pf[4];
    auto ldg_pf = [&](int c) {
#pragma unroll
        for (int q = 0; q < 4; q++) {
            float4 v = make_float4(0.f, 0.f, 0.f, 0.f);
            if (pok[q]) v = *reinterpret_cast<const float4*>(pb[q] + c * 64);
            pf[q] = v;
        }
    };

    if (C > 0) { comp_base(t0); ldg_pf(0); }

    float acc[2][6][4];
    const uint32_t Wm = sb + (uint32_t)SM_W;

    for (int cc = 0; cc < C; ++cc) {
        const int t = t0 + cc / 3;
        const int c = cc - 3 * (cc / 3);
        const uint32_t sA = sb + (uint32_t)(SM_A + (cc & 1) * A_STAGE);

        // ---- STS: convert pf -> fp16 staged (swizzled for ldmatrix) ----
#pragma unroll
        for (int q = 0; q < 4; q++) {
            uint32_t u0 = cvt_h2(pf[q].x, pf[q].y);
            uint32_t u1 = cvt_h2(pf[q].z, pf[q].w);
            int r  = rq[q], ci = cq[q];
            uint32_t off = (uint32_t)(r * 128 + (((ci >> 1) ^ (r & 7)) << 4) +
                                      ((ci & 1) << 3));
            asm volatile("st.shared.v2.b32 [%0], {%1,%2};"
                         :: "r"(sA + off), "r"(u0), "r"(u1) : "memory");
        }
        __syncthreads();

        // ---- prefetch next chunk (flies during MMA below) ----
        {
            int nc2 = cc + 1;
            if (nc2 < C) {
                int c2 = nc2 - 3 * (nc2 / 3);
                if (c2 == 0) comp_base(t + 1);
                ldg_pf(c2);
            }
        }

        if (c == 0) {
#pragma unroll
            for (int mi = 0; mi < 2; mi++)
#pragma unroll
                for (int nb = 0; nb < 6; nb++)
#pragma unroll
                    for (int j = 0; j < 4; j++) acc[mi][nb][j] = 0.0f;
        }

        // ---- MMA over this 64-col chunk ----
#pragma unroll
        for (int ki = 0; ki < 4; ki++) {
            // B fragments: 48 cols for this warp, 16-k slice
            const int cib = c * 8 + ki * 2;
            uint32_t bfr[6][2];
#pragma unroll
            for (int nb2 = 0; nb2 < 3; nb2++) {
                int nrow = 48 * wn + nb2 * 16 + 8 * (lane >> 4) + (lane & 7);
                int ci   = cib + ((lane >> 3) & 1);
                uint32_t addr = Wm + (uint32_t)(nrow * 384 + ((ci ^ (nrow & 7)) << 4));
                ldsm4(bfr[2 * nb2][0], bfr[2 * nb2][1],
                      bfr[2 * nb2 + 1][0], bfr[2 * nb2 + 1][1], addr);
            }
#pragma unroll
            for (int mi = 0; mi < 2; mi++) {
                // A fragment via ldmatrix from fp16 staging
                int rA  = 32 * wm + 16 * mi + (lane & 7) + 8 * ((lane >> 3) & 1);
                int cia = ki * 2 + (lane >> 4);
                uint32_t addr = sA + (uint32_t)(rA * 128 + ((cia ^ (rA & 7)) << 4));
                uint32_t a[4];
                ldsm4(a[0], a[1], a[2], a[3], addr);
#pragma unroll
                for (int nb = 0; nb < 6; nb++) mma16816(acc[mi][nb], a, bfr[nb]);
            }
        }

        // ---- epilogue on last chunk of tile ----
        if (c == 2) {
            const int g  = lane >> 2;
            const int t4 = lane & 3;
#pragma unroll
            for (int mi = 0; mi < 2; mi++) {
#pragma unroll
                for (int half = 0; half < 2; half++) {
                    int r    = 32 * wm + 16 * mi + 8 * half + g;
                    int grow = t * TILE_M + r;
                    if (grow < rows) {
                        unsigned gr   = (unsigned)grow;
                        unsigned node = row_to_node(gr, d);
                        unsigned sub  = gr - node * (unsigned)d;
                        float* po = out + (size_t)node * FEAT + segoff + sub * 192 +
                                    48 * wn + t4 * 2;
#pragma unroll
                        for (int nb = 0; nb < 6; nb++) {
                            float2 v = make_float2(acc[mi][nb][2 * half],
                                                   acc[mi][nb][2 * half + 1]);
                            *reinterpret_cast<float2*>(po + nb * 8) = v;
                        }
                    }
                }
            }
        }
    }
}

// ======================= launch =======================
extern "C" void kernel_launch(void* const* d_in, const int* in_sizes, int n_in,
                              void* d_out, int out_size) {
    const float* x  = (const float*)d_in[0];
    const float* Wb = (const float*)d_in[1];
    const float* WA = (const float*)d_in[2];
    const float* WB = (const float*)d_in[3];
    float* out = (float*)d_out;
    int n = in_sizes[0] / FEAT;

    static bool attr_set = false;
    if (!attr_set) {
        cudaFuncSetAttribute(lora_linear_main,
                             cudaFuncAttributeMaxDynamicSharedMemorySize, SMEM_TOTAL);
        attr_set = true;
    }

    prep_weights_kernel<<<(3 * MUL * MUL + 255) / 256, 256>>>(Wb, WA, WB);
    lora_linear_main<<<NCTA, NTHR, SMEM_TOTAL>>>(x, out, n);
}